// round 3
// baseline (speedup 1.0000x reference)
#include <cuda_runtime.h>
#include <cuda_bf16.h>
#include <cstdint>

typedef unsigned long long u64;

#define N_PTS 16384
#define M_CTR 4096
#define NNB   32
#define R2F   0.04f
#define NROWS (M_CTR*NNB)
#define KP    144
#define CAP   256
#define NBLK  128            // spatial blocks for lazy FPS
#define BPTS  128            // points per block

// ---------------- device scratch ----------------------------------------
__device__ __align__(16) float4 g_pos4[N_PTS];     // original order, .w unused
__device__ __align__(16) float4 g_spos4[N_PTS];    // morton order, .w = orig idx bits
__device__ __align__(16) float4 g_blo[NBLK];
__device__ __align__(16) float4 g_bhi[NBLK];
__device__ __align__(16) float4 g_center[M_CTR];
__device__ int   g_cols[NROWS];
__device__ __align__(16) float g_W1p[KP*128];
__device__ __align__(16) float g_W2p[KP*128];
__device__ __align__(16) float g_W3p[KP*256];
__device__ __align__(16) float g_A [(size_t)NROWS*KP];
__device__ __align__(16) float g_H1[(size_t)NROWS*KP];
__device__ __align__(16) float g_H2[(size_t)NROWS*KP];
__device__ __align__(16) float g_H3[(size_t)NROWS*256];

// ---------------- f32x2 helpers -----------------------------------------
__device__ __forceinline__ u64 pk(float lo, float hi) {
    u64 r; asm("mov.b64 %0,{%1,%2};" : "=l"(r) : "f"(lo), "f"(hi)); return r;
}
__device__ __forceinline__ void upk(float& lo, float& hi, u64 v) {
    asm("mov.b64 {%0,%1},%2;" : "=f"(lo), "=f"(hi) : "l"(v));
}
__device__ __forceinline__ u64 add2(u64 a, u64 b) {
    u64 r; asm("add.rn.f32x2 %0,%1,%2;" : "=l"(r) : "l"(a), "l"(b)); return r;
}
__device__ __forceinline__ u64 mul2(u64 a, u64 b) {
    u64 r; asm("mul.rn.f32x2 %0,%1,%2;" : "=l"(r) : "l"(a), "l"(b)); return r;
}
__device__ __forceinline__ u64 fma2(u64 a, u64 b, u64 c) {
    u64 r; asm("fma.rn.f32x2 %0,%1,%2,%3;" : "=l"(r) : "l"(a), "l"(b), "l"(c)); return r;
}
// key = (positive float bits << 32) | ~oidx : u64 max == (max val, tie -> min oidx)
__device__ __forceinline__ u64 mkkey(float v, int oidx) {
    return ((u64)__float_as_uint(v) << 32) | (u64)(unsigned)(~oidx);
}

// ---------------- prep ----------------------------------------------------
__global__ void __launch_bounds__(256) prep_kernel(
    const float* __restrict__ x,
    const float* __restrict__ W1, const float* __restrict__ b1,
    const float* __restrict__ W2, const float* __restrict__ b2,
    const float* __restrict__ W3, const float* __restrict__ b3)
{
    int i = blockIdx.x * 256 + threadIdx.x;
    if (i < N_PTS) {
        const float* row = x + (size_t)i * 131;
        g_pos4[i] = make_float4(row[0], row[1], row[2], 0.f);
    }
    if (i < KP * 128) {
        int k = i >> 7, j = i & 127;
        g_W1p[i] = (k < 131) ? W1[k * 128 + j] : (k == 131 ? b1[j] : 0.f);
        g_W2p[i] = (k < 128) ? W2[k * 128 + j] : (k == 128 ? b2[j] : 0.f);
    }
    if (i < KP * 256) {
        int k = i >> 8, j = i & 255;
        g_W3p[i] = (k < 128) ? W3[k * 256 + j] : (k == 128 ? b3[j] : 0.f);
    }
}

__global__ void __launch_bounds__(256) pad_kernel() {
    int row = blockIdx.x * 256 + threadIdx.x;
    if (row >= NROWS) return;
    float4* p1 = (float4*)(g_H1 + (size_t)row * KP + 128);
    float4* p2 = (float4*)(g_H2 + (size_t)row * KP + 128);
    float4 one0 = make_float4(1.f, 0.f, 0.f, 0.f);
    float4 z    = make_float4(0.f, 0.f, 0.f, 0.f);
    p1[0] = one0; p1[1] = z; p1[2] = z; p1[3] = z;
    p2[0] = one0; p2[1] = z; p2[2] = z; p2[3] = z;
}

// ---------------- morton sort (single CTA bitonic) ------------------------
__device__ __forceinline__ unsigned spread3(unsigned v) {
    v &= 0x3ffu;
    v = (v | (v << 16)) & 0x30000ffu;
    v = (v | (v << 8))  & 0x300f00fu;
    v = (v | (v << 4))  & 0x30c30c3u;
    v = (v | (v << 2))  & 0x9249249u;
    return v;
}

__global__ void __launch_bounds__(1024, 1) sort_kernel() {
    extern __shared__ u64 s_key[];                  // 16384 keys = 128KB
    __shared__ float s_r[192];
    __shared__ float3 s_lo, s_sc;
    int tid = threadIdx.x, lane = tid & 31, warp = tid >> 5;

    // global bbox (accuracy irrelevant for correctness)
    float mn[3] = {1e30f, 1e30f, 1e30f}, mx[3] = {-1e30f, -1e30f, -1e30f};
    for (int i = tid; i < N_PTS; i += 1024) {
        float4 p = g_pos4[i];
        mn[0] = fminf(mn[0], p.x); mx[0] = fmaxf(mx[0], p.x);
        mn[1] = fminf(mn[1], p.y); mx[1] = fmaxf(mx[1], p.y);
        mn[2] = fminf(mn[2], p.z); mx[2] = fmaxf(mx[2], p.z);
    }
#pragma unroll
    for (int o = 16; o; o >>= 1)
#pragma unroll
        for (int c = 0; c < 3; c++) {
            mn[c] = fminf(mn[c], __shfl_xor_sync(0xffffffffu, mn[c], o));
            mx[c] = fmaxf(mx[c], __shfl_xor_sync(0xffffffffu, mx[c], o));
        }
    if (lane == 0)
#pragma unroll
        for (int c = 0; c < 3; c++) { s_r[c * 32 + warp] = mn[c]; s_r[96 + c * 32 + warp] = mx[c]; }
    __syncthreads();
    if (tid == 0) {
        float lo[3], hi[3];
#pragma unroll
        for (int c = 0; c < 3; c++) {
            lo[c] = 1e30f; hi[c] = -1e30f;
            for (int w = 0; w < 32; w++) {
                lo[c] = fminf(lo[c], s_r[c * 32 + w]);
                hi[c] = fmaxf(hi[c], s_r[96 + c * 32 + w]);
            }
        }
        s_lo = make_float3(lo[0], lo[1], lo[2]);
        s_sc = make_float3(1023.f / fmaxf(hi[0] - lo[0], 1e-9f),
                           1023.f / fmaxf(hi[1] - lo[1], 1e-9f),
                           1023.f / fmaxf(hi[2] - lo[2], 1e-9f));
    }
    __syncthreads();
    for (int i = tid; i < N_PTS; i += 1024) {
        float4 p = g_pos4[i];
        unsigned ix = (unsigned)fminf(fmaxf((p.x - s_lo.x) * s_sc.x, 0.f), 1023.f);
        unsigned iy = (unsigned)fminf(fmaxf((p.y - s_lo.y) * s_sc.y, 0.f), 1023.f);
        unsigned iz = (unsigned)fminf(fmaxf((p.z - s_lo.z) * s_sc.z, 0.f), 1023.f);
        unsigned code = (spread3(ix) << 2) | (spread3(iy) << 1) | spread3(iz);
        s_key[i] = ((u64)code << 32) | (unsigned)i;
    }
    __syncthreads();
    for (int kk = 2; kk <= N_PTS; kk <<= 1) {
        for (int j = kk >> 1; j > 0; j >>= 1) {
            for (int t = tid; t < N_PTS / 2; t += 1024) {
                int i = ((t & ~(j - 1)) << 1) | (t & (j - 1));
                int r = i | j;
                u64 a = s_key[i], b = s_key[r];
                bool up = ((i & kk) == 0);
                if ((a > b) == up) { s_key[i] = b; s_key[r] = a; }
            }
            __syncthreads();
        }
    }
    for (int i = tid; i < N_PTS; i += 1024) {
        unsigned oi = (unsigned)s_key[i];
        float4 p = g_pos4[oi];
        p.w = __int_as_float((int)oi);
        g_spos4[i] = p;
    }
    __syncthreads();
    // per-block exact bbox
    for (int b = warp; b < NBLK; b += 32) {
        float l0 = 1e30f, l1 = 1e30f, l2 = 1e30f, h0 = -1e30f, h1 = -1e30f, h2 = -1e30f;
#pragma unroll
        for (int q = 0; q < 4; q++) {
            float4 p = g_spos4[b * BPTS + q * 32 + lane];
            l0 = fminf(l0, p.x); h0 = fmaxf(h0, p.x);
            l1 = fminf(l1, p.y); h1 = fmaxf(h1, p.y);
            l2 = fminf(l2, p.z); h2 = fmaxf(h2, p.z);
        }
#pragma unroll
        for (int o = 16; o; o >>= 1) {
            l0 = fminf(l0, __shfl_xor_sync(0xffffffffu, l0, o));
            l1 = fminf(l1, __shfl_xor_sync(0xffffffffu, l1, o));
            l2 = fminf(l2, __shfl_xor_sync(0xffffffffu, l2, o));
            h0 = fmaxf(h0, __shfl_xor_sync(0xffffffffu, h0, o));
            h1 = fmaxf(h1, __shfl_xor_sync(0xffffffffu, h1, o));
            h2 = fmaxf(h2, __shfl_xor_sync(0xffffffffu, h2, o));
        }
        if (lane == 0) {
            g_blo[b] = make_float4(l0, l1, l2, 0.f);
            g_bhi[b] = make_float4(h0, h1, h2, 0.f);
        }
    }
}

// ---------------- lazy blocked FPS (single CTA, 512 thr) ------------------
__device__ __forceinline__ u64 refresh_block(
    int b, int k, float* s_mind, const float4* s_centers,
    const float4* s_blo, const float4* s_bhi,
    float* s_ub, int* s_lastk, unsigned char* s_refr)
{
    int lane = threadIdx.x & 31;
    int base = b * BPTS;
    float4 p0 = g_spos4[base + lane];
    float4 p1 = g_spos4[base + 32 + lane];
    float4 p2 = g_spos4[base + 64 + lane];
    float4 p3 = g_spos4[base + 96 + lane];
    u64 PX0 = pk(p0.x, p1.x), PY0 = pk(p0.y, p1.y), PZ0 = pk(p0.z, p1.z);
    u64 PX1 = pk(p2.x, p3.x), PY1 = pk(p2.y, p3.y), PZ1 = pk(p2.z, p3.z);
    float m0 = s_mind[base + lane],      m1 = s_mind[base + 32 + lane];
    float m2 = s_mind[base + 64 + lane], m3 = s_mind[base + 96 + lane];
    float4 lo = s_blo[b], hi = s_bhi[b];
    float U = s_ub[b];
    int k0 = s_lastk[b];

    for (int kk = k0; kk < k; kk += 32) {
        int myc = kk + lane;
        bool sv = false;
        float4 c = make_float4(0.f, 0.f, 0.f, 0.f);
        if (myc < k) {
            c = s_centers[myc];
            // monotone-safe lower bound on d2(c, any point in block), same op order
            float ex = fmaxf(fmaxf(__fsub_rn(lo.x, c.x), __fsub_rn(c.x, hi.x)), 0.f);
            float ey = fmaxf(fmaxf(__fsub_rn(lo.y, c.y), __fsub_rn(c.y, hi.y)), 0.f);
            float ez = fmaxf(fmaxf(__fsub_rn(lo.z, c.z), __fsub_rn(c.z, hi.z)), 0.f);
            float bd = __fadd_rn(__fadd_rn(__fmul_rn(ex, ex), __fmul_rn(ey, ey)),
                                 __fmul_rn(ez, ez));
            sv = bd < U;            // skip permanently if bd >= U
        }
        unsigned msk = __ballot_sync(0xffffffffu, sv);
        while (msk) {
            int src = __ffs(msk) - 1; msk &= msk - 1;
            float cx = __shfl_sync(0xffffffffu, c.x, src);
            float cy = __shfl_sync(0xffffffffu, c.y, src);
            float cz = __shfl_sync(0xffffffffu, c.z, src);
            u64 ncx = pk(-cx, -cx), ncy = pk(-cy, -cy), ncz = pk(-cz, -cz);
            // p + (-c) == p - c bitwise; rn mul/add, order (x2+y2)+z2
            u64 dx = add2(PX0, ncx), dy = add2(PY0, ncy), dz = add2(PZ0, ncz);
            u64 s  = add2(add2(mul2(dx, dx), mul2(dy, dy)), mul2(dz, dz));
            float d0, d1; upk(d0, d1, s);
            m0 = fminf(m0, d0); m1 = fminf(m1, d1);
            dx = add2(PX1, ncx); dy = add2(PY1, ncy); dz = add2(PZ1, ncz);
            s  = add2(add2(mul2(dx, dx), mul2(dy, dy)), mul2(dz, dz));
            upk(d0, d1, s);
            m2 = fminf(m2, d0); m3 = fminf(m3, d1);
        }
    }
    s_mind[base + lane] = m0;      s_mind[base + 32 + lane] = m1;
    s_mind[base + 64 + lane] = m2; s_mind[base + 96 + lane] = m3;

    u64 key = mkkey(m0, __float_as_int(p0.w));
    u64 t;
    t = mkkey(m1, __float_as_int(p1.w)); if (t > key) key = t;
    t = mkkey(m2, __float_as_int(p2.w)); if (t > key) key = t;
    t = mkkey(m3, __float_as_int(p3.w)); if (t > key) key = t;
#pragma unroll
    for (int o = 16; o; o >>= 1) {
        u64 ok = __shfl_xor_sync(0xffffffffu, key, o);
        if (ok > key) key = ok;
    }
    if (lane == 0) {
        s_ub[b] = __uint_as_float((unsigned)(key >> 32));
        s_lastk[b] = k;
        s_refr[b] = 1;
    }
    return key;
}

__global__ void __launch_bounds__(512, 1) fps_kernel() {
    extern __shared__ char sm_raw[];
    float*  s_mind    = (float*)sm_raw;                        // 64KB
    float4* s_centers = (float4*)(sm_raw + 65536);             // 64KB
    __shared__ __align__(16) float4 s_blo[NBLK];
    __shared__ __align__(16) float4 s_bhi[NBLK];
    __shared__ float s_ub[NBLK];
    __shared__ int   s_lastk[NBLK];
    __shared__ unsigned char s_refr[NBLK];
    __shared__ int   s_list[NBLK];
    __shared__ u64   s_cand[16];
    __shared__ int   s_cnt;
    __shared__ u64   s_bestkey;
    __shared__ float s_prevbest;

    int tid = threadIdx.x, lane = tid & 31, warp = tid >> 5;

    for (int i = tid; i < N_PTS; i += 512) s_mind[i] = __int_as_float(0x7f800000);
    if (tid < NBLK) {
        s_ub[tid] = __int_as_float(0x7f800000);
        s_lastk[tid] = 0;
        s_refr[tid] = 0;
        s_blo[tid] = g_blo[tid];
        s_bhi[tid] = g_bhi[tid];
    }
    if (tid == 0) {
        float4 c0 = g_pos4[0];
        s_centers[0] = c0;
        g_center[0] = c0;
        s_prevbest = __int_as_float(0x7f800000);
        s_bestkey = 0;
    }
    __syncthreads();

    for (int k = 1; k < M_CTR; k++) {
        // per-step reset
        if (tid < NBLK) s_refr[tid] = 0;
        if (tid == 0) s_bestkey = 0;

        while (true) {
            __syncthreads();                                   // (A)
            if (warp == 0) {
                u64 bk = s_bestkey;
                float thr = (bk == 0) ? s_prevbest
                                      : __uint_as_float((unsigned)(bk >> 32));
                int cnt = 0;
                float fu = -1.f; int fb = -1;                  // fallback argmax-ub
#pragma unroll
                for (int q = 0; q < 4; q++) {
                    int b = q * 32 + lane;
                    bool unr = (s_refr[b] == 0);
                    float u = s_ub[b];
                    bool el = unr && (u >= thr);
                    unsigned m = __ballot_sync(0xffffffffu, el);
                    if (el) s_list[cnt + __popc(m & ((1u << lane) - 1u))] = b;
                    cnt += __popc(m);
                    if (unr && u > fu) { fu = u; fb = b; }
                }
                if (cnt == 0 && bk == 0) {                     // safety fallback
#pragma unroll
                    for (int o = 16; o; o >>= 1) {
                        float ou = __shfl_xor_sync(0xffffffffu, fu, o);
                        int   ob = __shfl_xor_sync(0xffffffffu, fb, o);
                        if (ou > fu || (ou == fu && ob >= 0 && (fb < 0 || ob < fb))) { fu = ou; fb = ob; }
                    }
                    if (fb >= 0) { s_list[0] = fb; cnt = 1; }
                }
                if (lane == 0) s_cnt = cnt;
            }
            __syncthreads();                                   // (B)
            int cnt = s_cnt;
            if (cnt == 0) break;
            u64 mycand = 0;
            for (int e = warp; e < cnt; e += 16)
                mycand = max(mycand,
                             refresh_block(s_list[e], k, s_mind, s_centers,
                                           s_blo, s_bhi, s_ub, s_lastk, s_refr));
            if (lane == 0) s_cand[warp] = mycand;
            __syncthreads();                                   // (C)
            if (tid == 0) {
                u64 m = s_bestkey;
#pragma unroll
                for (int w = 0; w < 16; w++) if (s_cand[w] > m) m = s_cand[w];
                s_bestkey = m;
            }
        }
        if (tid == 0) {
            u64 bk = s_bestkey;
            int oidx = (int)(~(unsigned)(bk & 0xffffffffu));
            float4 c = g_pos4[oidx];
            s_centers[k] = c;
            g_center[k] = c;
            s_prevbest = __uint_as_float((unsigned)(bk >> 32));
        }
        // no barrier needed here: wave-top (A) of next step separates
    }
}

// ---------------- radius-KNN ----------------------------------------------
__global__ void __launch_bounds__(128) knn_kernel() {
    extern __shared__ float4 s_t[];                  // 4096 float4 = 64KB
    __shared__ u64 s_list[4][CAP];
    int tid = threadIdx.x, lane = tid & 31, warp = tid >> 5;
    int c = blockIdx.x * 4 + warp;
    float4 ct = g_center[c];

    int cnt = 0;
    for (int tile = 0; tile < 4; tile++) {
        __syncthreads();
        for (int i = tid; i < 4096; i += 128) s_t[i] = g_pos4[tile * 4096 + i];
        __syncthreads();
        for (int i = lane; i < 4096; i += 32) {
            float4 p = s_t[i];
            float dx = __fsub_rn(ct.x, p.x);
            float dy = __fsub_rn(ct.y, p.y);
            float dz = __fsub_rn(ct.z, p.z);
            float d2 = __fadd_rn(__fadd_rn(__fmul_rn(dx, dx), __fmul_rn(dy, dy)),
                                 __fmul_rn(dz, dz));
            bool ok = d2 <= R2F;
            unsigned m = __ballot_sync(0xffffffffu, ok);
            if (ok) {
                int pos = cnt + __popc(m & ((1u << lane) - 1u));
                if (pos < CAP)
                    s_list[warp][pos] =
                        ((u64)__float_as_uint(d2) << 32) | (unsigned)(tile * 4096 + i);
            }
            cnt += __popc(m);
        }
    }
    if (cnt > CAP) cnt = CAP;
    __syncwarp();

    if (cnt <= NNB) {
        int v = (lane < cnt) ? (int)(unsigned)(s_list[warp][lane] & 0xffffffffu) : -1;
        g_cols[c * NNB + lane] = v;
    } else {
        for (int i = lane; i < cnt; i += 32) {
            u64 ki = s_list[warp][i];
            int rank = 0;
            for (int j = 0; j < cnt; j++) rank += (s_list[warp][j] < ki);
            if (rank < NNB)
                g_cols[c * NNB + rank] = (int)(unsigned)(ki & 0xffffffffu);
        }
    }
}

// ---------------- gather ---------------------------------------------------
__global__ void __launch_bounds__(128) gather_kernel(const float* __restrict__ x) {
    int row  = blockIdx.x * 4 + (threadIdx.x >> 5);
    int lane = threadIdx.x & 31;
    int c    = row >> 5;
    int col  = g_cols[row];
    float* a = g_A + (size_t)row * KP;
    float4 v = make_float4(0.f, 0.f, 0.f, 0.f);
    if (col >= 0) {
        const float* xr = x + (size_t)col * 131 + 3 + 4 * lane;
        v = make_float4(xr[0], xr[1], xr[2], xr[3]);
    }
    ((float4*)a)[lane] = v;
    if (lane < 4) {
        float4 e = make_float4(0.f, 0.f, 0.f, 0.f);
        if (lane == 0) {
            if (col >= 0) {
                float4 p = g_pos4[col]; float4 ct = g_center[c];
                e = make_float4(p.x - ct.x, p.y - ct.y, p.z - ct.z, 1.0f);
            } else e = make_float4(0.f, 0.f, 0.f, 1.0f);
        }
        ((float4*)a)[32 + lane] = e;
    }
}

// ---------------- tiled fp32 GEMM + relu -----------------------------------
template<int L>
__global__ void __launch_bounds__(256) sgemm_kernel() {
    const float* A = (L == 0) ? g_A  : (L == 1) ? g_H1 : g_H2;
    const float* B = (L == 0) ? g_W1p : (L == 1) ? g_W2p : g_W3p;
    float*       C = (L == 0) ? g_H1 : (L == 1) ? g_H2 : g_H3;
    const int ldb = (L == 2) ? 256 : 128;
    const int ldc = (L == 2) ? 256 : KP;

    __shared__ __align__(16) float As[16][132];
    __shared__ __align__(16) float Bs[16][132];
    int t  = threadIdx.x;
    int tx = t & 15, ty = t >> 4;
    size_t bRow = (size_t)blockIdx.x * 128;
    int    bCol = blockIdx.y * 128;

    u64 acc[8][4];
#pragma unroll
    for (int i = 0; i < 8; i++)
#pragma unroll
        for (int p = 0; p < 4; p++) acc[i][p] = 0ull;

    for (int k0 = 0; k0 < KP; k0 += 16) {
#pragma unroll
        for (int e2 = 0; e2 < 2; e2++) {
            int e = t * 2 + e2;
            int r = e >> 2, c4 = e & 3;
            float4 f = *(const float4*)(A + (bRow + r) * KP + k0 + c4 * 4);
            As[c4 * 4 + 0][r] = f.x; As[c4 * 4 + 1][r] = f.y;
            As[c4 * 4 + 2][r] = f.z; As[c4 * 4 + 3][r] = f.w;
        }
#pragma unroll
        for (int e2 = 0; e2 < 2; e2++) {
            int e = t * 2 + e2;
            int r = e >> 5, c4 = e & 31;
            *(float4*)&Bs[r][c4 * 4] =
                *(const float4*)(B + (size_t)(k0 + r) * ldb + bCol + c4 * 4);
        }
        __syncthreads();
#pragma unroll
        for (int kk = 0; kk < 16; kk++) {
            float a[8]; u64 b[4];
            const u64* bp = (const u64*)&Bs[kk][tx * 8];
#pragma unroll
            for (int p = 0; p < 4; p++) b[p] = bp[p];
#pragma unroll
            for (int i = 0; i < 8; i++) a[i] = As[kk][ty * 8 + i];
#pragma unroll
            for (int i = 0; i < 8; i++) {
                u64 aa = pk(a[i], a[i]);
#pragma unroll
                for (int p = 0; p < 4; p++) acc[i][p] = fma2(aa, b[p], acc[i][p]);
            }
        }
        __syncthreads();
    }
#pragma unroll
    for (int i = 0; i < 8; i++) {
        float* cr = C + (bRow + ty * 8 + i) * (size_t)ldc + bCol + tx * 8;
#pragma unroll
        for (int p = 0; p < 4; p++) {
            float lo, hi; upk(lo, hi, acc[i][p]);
            ((float2*)cr)[p] = make_float2(fmaxf(lo, 0.f), fmaxf(hi, 0.f));
        }
    }
}

// ---------------- masked max-pool -------------------------------------------
__global__ void __launch_bounds__(256) pool_kernel(float* __restrict__ out) {
    int c = blockIdx.x, j = threadIdx.x;
    float acc = __int_as_float(0xff800000);
    bool any = false;
#pragma unroll 4
    for (int s = 0; s < NNB; s++) {
        bool v  = g_cols[c * NNB + s] >= 0;
        float h = g_H3[(size_t)(c * NNB + s) * 256 + j];
        if (v) { any = true; acc = fmaxf(acc, h); }
    }
    out[(size_t)c * 256 + j] = any ? acc : 0.0f;
}

// ---------------- launcher ----------------------------------------------
extern "C" void kernel_launch(void* const* d_in, const int* in_sizes, int n_in,
                              void* d_out, int out_size) {
    const float* x  = (const float*)d_in[0];
    const float* W1 = (const float*)d_in[1];
    const float* b1 = (const float*)d_in[2];
    const float* W2 = (const float*)d_in[3];
    const float* b2 = (const float*)d_in[4];
    const float* W3 = (const float*)d_in[5];
    const float* b3 = (const float*)d_in[6];
    float* out = (float*)d_out;

    cudaFuncSetAttribute(sort_kernel, cudaFuncAttributeMaxDynamicSharedMemorySize, 131072);
    cudaFuncSetAttribute(fps_kernel,  cudaFuncAttributeMaxDynamicSharedMemorySize, 131072);
    cudaFuncSetAttribute(knn_kernel,  cudaFuncAttributeMaxDynamicSharedMemorySize, 65536);

    prep_kernel<<<144, 256>>>(x, W1, b1, W2, b2, W3, b3);
    pad_kernel<<<(NROWS + 255) / 256, 256>>>();
    sort_kernel<<<1, 1024, 131072>>>();
    fps_kernel<<<1, 512, 131072>>>();
    knn_kernel<<<M_CTR / 4, 128, 65536>>>();
    gather_kernel<<<NROWS / 4, 128>>>(x);
    sgemm_kernel<0><<<dim3(NROWS / 128, 1), 256>>>();
    sgemm_kernel<1><<<dim3(NROWS / 128, 1), 256>>>();
    sgemm_kernel<2><<<dim3(NROWS / 128, 2), 256>>>();
    pool_kernel<<<M_CTR, 256>>>(out);
}

// round 4
// speedup vs baseline: 3.2407x; 3.2407x over previous
#include <cuda_runtime.h>
#include <cuda_bf16.h>
#include <cstdint>

typedef unsigned long long u64;

#define N_PTS 16384
#define M_CTR 4096
#define NNB   32
#define R2F   0.04f
#define NROWS (M_CTR*NNB)
#define KP    144
#define CAP   256
#define CLSZ  8               // FPS cluster size
#define PPC   (N_PTS/CLSZ)    // 2048 points per CTA
#define FPT   8               // points per thread (256 thr/CTA)

// ---------------- device scratch ----------------------------------------
__device__ __align__(16) float4 g_pos4[N_PTS];
__device__ __align__(16) float4 g_center[M_CTR];
__device__ int   g_cols[NROWS];
__device__ __align__(16) float g_W1p[KP*128];
__device__ __align__(16) float g_W2p[KP*128];
__device__ __align__(16) float g_W3p[KP*256];
__device__ __align__(16) float g_A [(size_t)NROWS*KP];
__device__ __align__(16) float g_H1[(size_t)NROWS*KP];
__device__ __align__(16) float g_H2[(size_t)NROWS*KP];
__device__ __align__(16) float g_H3[(size_t)NROWS*256];

// ---------------- f32x2 helpers -----------------------------------------
__device__ __forceinline__ u64 pk(float lo, float hi) {
    u64 r; asm("mov.b64 %0,{%1,%2};" : "=l"(r) : "f"(lo), "f"(hi)); return r;
}
__device__ __forceinline__ void upk(float& lo, float& hi, u64 v) {
    asm("mov.b64 {%0,%1},%2;" : "=f"(lo), "=f"(hi) : "l"(v));
}
__device__ __forceinline__ u64 add2(u64 a, u64 b) {
    u64 r; asm("add.rn.f32x2 %0,%1,%2;" : "=l"(r) : "l"(a), "l"(b)); return r;
}
__device__ __forceinline__ u64 mul2(u64 a, u64 b) {
    u64 r; asm("mul.rn.f32x2 %0,%1,%2;" : "=l"(r) : "l"(a), "l"(b)); return r;
}
__device__ __forceinline__ u64 fma2(u64 a, u64 b, u64 c) {
    u64 r; asm("fma.rn.f32x2 %0,%1,%2,%3;" : "=l"(r) : "l"(a), "l"(b), "l"(c)); return r;
}
// key = (positive f32 bits << 32) | ~oidx : u64 max == (max val, tie -> min idx)
__device__ __forceinline__ u64 mkkey(float v, int oidx) {
    return ((u64)__float_as_uint(v) << 32) | (u64)(unsigned)(~oidx);
}

// ---------------- cluster / mbarrier PTX helpers -------------------------
__device__ __forceinline__ unsigned sh_u32(const void* p) {
    return (unsigned)__cvta_generic_to_shared(p);
}
__device__ __forceinline__ unsigned mapa_sh(unsigned addr, unsigned rank) {
    unsigned r;
    asm("mapa.shared::cluster.u32 %0, %1, %2;" : "=r"(r) : "r"(addr), "r"(rank));
    return r;
}
__device__ __forceinline__ void st_cl_u64(unsigned a, u64 v) {
    asm volatile("st.shared::cluster.u64 [%0], %1;" :: "r"(a), "l"(v) : "memory");
}
__device__ __forceinline__ void st_cl_b32(unsigned a, unsigned v) {
    asm volatile("st.shared::cluster.b32 [%0], %1;" :: "r"(a), "r"(v) : "memory");
}
__device__ __forceinline__ void mbar_init(unsigned a, unsigned cnt) {
    asm volatile("mbarrier.init.shared.b64 [%0], %1;" :: "r"(a), "r"(cnt) : "memory");
}
__device__ __forceinline__ void mbar_arrive_cluster(unsigned a) {
    asm volatile("mbarrier.arrive.release.cluster.shared::cluster.b64 _, [%0];"
                 :: "r"(a) : "memory");
}
__device__ __forceinline__ void mbar_wait_cluster(unsigned a, int phase) {
    asm volatile(
        "{\n\t"
        ".reg .pred P;\n\t"
        "W_%=:\n\t"
        "mbarrier.try_wait.parity.acquire.cluster.shared::cta.b64 P, [%0], %1, 0x989680;\n\t"
        "@P bra.uni D_%=;\n\t"
        "bra.uni W_%=;\n\t"
        "D_%=:\n\t"
        "}" :: "r"(a), "r"(phase) : "memory");
}
__device__ __forceinline__ void cluster_sync_all() {
    asm volatile("barrier.cluster.arrive.aligned;" ::: "memory");
    asm volatile("barrier.cluster.wait.aligned;" ::: "memory");
}

// ---------------- prep ----------------------------------------------------
__global__ void __launch_bounds__(256) prep_kernel(
    const float* __restrict__ x,
    const float* __restrict__ W1, const float* __restrict__ b1,
    const float* __restrict__ W2, const float* __restrict__ b2,
    const float* __restrict__ W3, const float* __restrict__ b3)
{
    int i = blockIdx.x * 256 + threadIdx.x;
    if (i < N_PTS) {
        const float* row = x + (size_t)i * 131;
        g_pos4[i] = make_float4(row[0], row[1], row[2], 0.f);
    }
    if (i < KP * 128) {
        int k = i >> 7, j = i & 127;
        g_W1p[i] = (k < 131) ? W1[k * 128 + j] : (k == 131 ? b1[j] : 0.f);
        g_W2p[i] = (k < 128) ? W2[k * 128 + j] : (k == 128 ? b2[j] : 0.f);
    }
    if (i < KP * 256) {
        int k = i >> 8, j = i & 255;
        g_W3p[i] = (k < 128) ? W3[k * 256 + j] : (k == 128 ? b3[j] : 0.f);
    }
}

__global__ void __launch_bounds__(256) pad_kernel() {
    int row = blockIdx.x * 256 + threadIdx.x;
    if (row >= NROWS) return;
    float4* p1 = (float4*)(g_H1 + (size_t)row * KP + 128);
    float4* p2 = (float4*)(g_H2 + (size_t)row * KP + 128);
    float4 one0 = make_float4(1.f, 0.f, 0.f, 0.f);
    float4 z    = make_float4(0.f, 0.f, 0.f, 0.f);
    p1[0] = one0; p1[1] = z; p1[2] = z; p1[3] = z;
    p2[0] = one0; p2[1] = z; p2[2] = z; p2[3] = z;
}

// ---------------- FPS: 8-CTA cluster, all state in registers --------------
__global__ void __launch_bounds__(256, 1) __cluster_dims__(CLSZ, 1, 1)
fps_kernel() {
    __shared__ __align__(16) u64    s_wkey[8];       // per-warp bests
    __shared__ __align__(16) float4 s_wxyz[8];
    __shared__ __align__(16) u64    s_mbk [2][CLSZ]; // mailbox keys (dbl buf)
    __shared__ __align__(16) float2 s_mbxy[2][CLSZ];
    __shared__ float                s_mbz [2][CLSZ];
    __shared__ __align__(8)  u64    s_bar [2];

    int tid = threadIdx.x, lane = tid & 31, warp = tid >> 5;
    unsigned rank;
    asm("mov.u32 %0, %%cluster_ctarank;" : "=r"(rank));
    int pbase = (int)rank * PPC + tid;

    // coords + min_d fully register-resident
    u64 PX[4], PY[4], PZ[4];
    float m[FPT];
#pragma unroll
    for (int q = 0; q < 4; q++) {
        float4 a = g_pos4[pbase + (2 * q) * 256];
        float4 b = g_pos4[pbase + (2 * q + 1) * 256];
        PX[q] = pk(a.x, b.x); PY[q] = pk(a.y, b.y); PZ[q] = pk(a.z, b.z);
        m[2 * q] = __int_as_float(0x7f800000);
        m[2 * q + 1] = __int_as_float(0x7f800000);
    }

    if (tid == 0) {
        mbar_init(sh_u32(&s_bar[0]), CLSZ);
        mbar_init(sh_u32(&s_bar[1]), CLSZ);
    }
    cluster_sync_all();     // barriers visible before any remote arrive

    float4 c0 = g_pos4[0];
    float cx = c0.x, cy = c0.y, cz = c0.z;
    if (rank == 0 && tid == 0) g_center[0] = make_float4(cx, cy, cz, 0.f);

    int par0 = 0, par1 = 0;

    for (int k = 1; k < M_CTR; k++) {
        int buf = k & 1;
        // --- packed exact distance update (rn ops, (x2+y2)+z2, p+(-c)) ---
        u64 ncx = pk(-cx, -cx), ncy = pk(-cy, -cy), ncz = pk(-cz, -cz);
#pragma unroll
        for (int q = 0; q < 4; q++) {
            u64 dx = add2(PX[q], ncx);
            u64 dy = add2(PY[q], ncy);
            u64 dz = add2(PZ[q], ncz);
            u64 s  = add2(add2(mul2(dx, dx), mul2(dy, dy)), mul2(dz, dz));
            float d0, d1; upk(d0, d1, s);
            m[2 * q]     = fminf(m[2 * q], d0);
            m[2 * q + 1] = fminf(m[2 * q + 1], d1);
        }
        // --- per-thread argmax (first index on tie) ---
        float vmax = m[0];
#pragma unroll
        for (int i = 1; i < FPT; i++) vmax = fmaxf(vmax, m[i]);
        int idx = 0;
#pragma unroll
        for (int i = FPT - 1; i >= 0; i--) if (m[i] == vmax) idx = i;
        u64 key = mkkey(vmax, pbase + idx * 256);
        float bx = 0.f, by = 0.f, bz = 0.f;
#pragma unroll
        for (int q = 0; q < 4; q++) {
            if ((idx >> 1) == q) {
                float lo, hi;
                upk(lo, hi, PX[q]); bx = (idx & 1) ? hi : lo;
                upk(lo, hi, PY[q]); by = (idx & 1) ? hi : lo;
                upk(lo, hi, PZ[q]); bz = (idx & 1) ? hi : lo;
            }
        }
        // --- warp bfly reduce carrying coords ---
#pragma unroll
        for (int o = 16; o; o >>= 1) {
            u64  ok = __shfl_xor_sync(0xffffffffu, key, o);
            float ox = __shfl_xor_sync(0xffffffffu, bx, o);
            float oy = __shfl_xor_sync(0xffffffffu, by, o);
            float oz = __shfl_xor_sync(0xffffffffu, bz, o);
            if (ok > key) { key = ok; bx = ox; by = oy; bz = oz; }
        }
        if (lane == 0) { s_wkey[warp] = key; s_wxyz[warp] = make_float4(bx, by, bz, 0.f); }
        __syncthreads();
        // --- CTA reduce in warp0, then scatter to all ranks' mailboxes ---
        if (warp == 0) {
            u64 kk = s_wkey[lane & 7];
            float4 w = s_wxyz[lane & 7];
#pragma unroll
            for (int o = 4; o; o >>= 1) {
                u64  ok = __shfl_xor_sync(0xffffffffu, kk, o);
                float ox = __shfl_xor_sync(0xffffffffu, w.x, o);
                float oy = __shfl_xor_sync(0xffffffffu, w.y, o);
                float oz = __shfl_xor_sync(0xffffffffu, w.z, o);
                if (ok > kk) { kk = ok; w.x = ox; w.y = oy; w.z = oz; }
            }
            if (lane < CLSZ) {
                unsigned dst = (unsigned)lane;
                unsigned ak = mapa_sh(sh_u32(&s_mbk [buf][rank]), dst);
                unsigned ax = mapa_sh(sh_u32(&s_mbxy[buf][rank]), dst);
                unsigned az = mapa_sh(sh_u32(&s_mbz [buf][rank]), dst);
                unsigned ab = mapa_sh(sh_u32(&s_bar [buf]),       dst);
                st_cl_u64(ak, kk);
                st_cl_u64(ax, pk(w.x, w.y));
                st_cl_b32(az, __float_as_uint(w.z));
                mbar_arrive_cluster(ab);
            }
        }
        // --- wait for all 8 contributions, pick global winner locally ---
        mbar_wait_cluster(sh_u32(&s_bar[buf]), buf ? par1 : par0);
        if (buf) par1 ^= 1; else par0 ^= 1;

        u64 best = s_mbk[buf][0];
        float2 wxy = s_mbxy[buf][0];
        float  wz  = s_mbz[buf][0];
#pragma unroll
        for (int r = 1; r < CLSZ; r++) {
            u64 kr = s_mbk[buf][r];
            if (kr > best) { best = kr; wxy = s_mbxy[buf][r]; wz = s_mbz[buf][r]; }
        }
        cx = wxy.x; cy = wxy.y; cz = wz;
        if (rank == 0 && tid == 0) g_center[k] = make_float4(cx, cy, cz, 0.f);
    }
    cluster_sync_all();
}

// ---------------- radius-KNN ----------------------------------------------
__global__ void __launch_bounds__(128) knn_kernel() {
    extern __shared__ float4 s_t[];                  // 4096 float4 = 64KB
    __shared__ u64 s_list[4][CAP];
    int tid = threadIdx.x, lane = tid & 31, warp = tid >> 5;
    int c = blockIdx.x * 4 + warp;
    float4 ct = g_center[c];

    int cnt = 0;
    for (int tile = 0; tile < 4; tile++) {
        __syncthreads();
        for (int i = tid; i < 4096; i += 128) s_t[i] = g_pos4[tile * 4096 + i];
        __syncthreads();
        for (int i = lane; i < 4096; i += 32) {
            float4 p = s_t[i];
            float dx = __fsub_rn(ct.x, p.x);
            float dy = __fsub_rn(ct.y, p.y);
            float dz = __fsub_rn(ct.z, p.z);
            float d2 = __fadd_rn(__fadd_rn(__fmul_rn(dx, dx), __fmul_rn(dy, dy)),
                                 __fmul_rn(dz, dz));
            bool ok = d2 <= R2F;
            unsigned mk = __ballot_sync(0xffffffffu, ok);
            if (ok) {
                int pos = cnt + __popc(mk & ((1u << lane) - 1u));
                if (pos < CAP)
                    s_list[warp][pos] =
                        ((u64)__float_as_uint(d2) << 32) | (unsigned)(tile * 4096 + i);
            }
            cnt += __popc(mk);
        }
    }
    if (cnt > CAP) cnt = CAP;
    __syncwarp();

    if (cnt <= NNB) {
        int v = (lane < cnt) ? (int)(unsigned)(s_list[warp][lane] & 0xffffffffu) : -1;
        g_cols[c * NNB + lane] = v;
    } else {
        for (int i = lane; i < cnt; i += 32) {
            u64 ki = s_list[warp][i];
            int rank = 0;
            for (int j = 0; j < cnt; j++) rank += (s_list[warp][j] < ki);
            if (rank < NNB)
                g_cols[c * NNB + rank] = (int)(unsigned)(ki & 0xffffffffu);
        }
    }
}

// ---------------- gather ---------------------------------------------------
__global__ void __launch_bounds__(128) gather_kernel(const float* __restrict__ x) {
    int row  = blockIdx.x * 4 + (threadIdx.x >> 5);
    int lane = threadIdx.x & 31;
    int c    = row >> 5;
    int col  = g_cols[row];
    float* a = g_A + (size_t)row * KP;
    float4 v = make_float4(0.f, 0.f, 0.f, 0.f);
    if (col >= 0) {
        const float* xr = x + (size_t)col * 131 + 3 + 4 * lane;
        v = make_float4(xr[0], xr[1], xr[2], xr[3]);
    }
    ((float4*)a)[lane] = v;
    if (lane < 4) {
        float4 e = make_float4(0.f, 0.f, 0.f, 0.f);
        if (lane == 0) {
            if (col >= 0) {
                float4 p = g_pos4[col]; float4 ct = g_center[c];
                e = make_float4(p.x - ct.x, p.y - ct.y, p.z - ct.z, 1.0f);
            } else e = make_float4(0.f, 0.f, 0.f, 1.0f);
        }
        ((float4*)a)[32 + lane] = e;
    }
}

// ---------------- tiled fp32 GEMM + relu -----------------------------------
template<int L>
__global__ void __launch_bounds__(256) sgemm_kernel() {
    const float* A = (L == 0) ? g_A  : (L == 1) ? g_H1 : g_H2;
    const float* B = (L == 0) ? g_W1p : (L == 1) ? g_W2p : g_W3p;
    float*       C = (L == 0) ? g_H1 : (L == 1) ? g_H2 : g_H3;
    const int ldb = (L == 2) ? 256 : 128;
    const int ldc = (L == 2) ? 256 : KP;

    __shared__ __align__(16) float As[16][132];
    __shared__ __align__(16) float Bs[16][132];
    int t  = threadIdx.x;
    int tx = t & 15, ty = t >> 4;
    size_t bRow = (size_t)blockIdx.x * 128;
    int    bCol = blockIdx.y * 128;

    u64 acc[8][4];
#pragma unroll
    for (int i = 0; i < 8; i++)
#pragma unroll
        for (int p = 0; p < 4; p++) acc[i][p] = 0ull;

    for (int k0 = 0; k0 < KP; k0 += 16) {
#pragma unroll
        for (int e2 = 0; e2 < 2; e2++) {
            int e = t * 2 + e2;
            int r = e >> 2, c4 = e & 3;
            float4 f = *(const float4*)(A + (bRow + r) * KP + k0 + c4 * 4);
            As[c4 * 4 + 0][r] = f.x; As[c4 * 4 + 1][r] = f.y;
            As[c4 * 4 + 2][r] = f.z; As[c4 * 4 + 3][r] = f.w;
        }
#pragma unroll
        for (int e2 = 0; e2 < 2; e2++) {
            int e = t * 2 + e2;
            int r = e >> 5, c4 = e & 31;
            *(float4*)&Bs[r][c4 * 4] =
                *(const float4*)(B + (size_t)(k0 + r) * ldb + bCol + c4 * 4);
        }
        __syncthreads();
#pragma unroll
        for (int kk = 0; kk < 16; kk++) {
            float a[8]; u64 b[4];
            const u64* bp = (const u64*)&Bs[kk][tx * 8];
#pragma unroll
            for (int p = 0; p < 4; p++) b[p] = bp[p];
#pragma unroll
            for (int i = 0; i < 8; i++) a[i] = As[kk][ty * 8 + i];
#pragma unroll
            for (int i = 0; i < 8; i++) {
                u64 aa = pk(a[i], a[i]);
#pragma unroll
                for (int p = 0; p < 4; p++) acc[i][p] = fma2(aa, b[p], acc[i][p]);
            }
        }
        __syncthreads();
    }
#pragma unroll
    for (int i = 0; i < 8; i++) {
        float* cr = C + (bRow + ty * 8 + i) * (size_t)ldc + bCol + tx * 8;
#pragma unroll
        for (int p = 0; p < 4; p++) {
            float lo, hi; upk(lo, hi, acc[i][p]);
            ((float2*)cr)[p] = make_float2(fmaxf(lo, 0.f), fmaxf(hi, 0.f));
        }
    }
}

// ---------------- masked max-pool -------------------------------------------
__global__ void __launch_bounds__(256) pool_kernel(float* __restrict__ out) {
    int c = blockIdx.x, j = threadIdx.x;
    float acc = __int_as_float(0xff800000);
    bool any = false;
#pragma unroll 4
    for (int s = 0; s < NNB; s++) {
        bool v  = g_cols[c * NNB + s] >= 0;
        float h = g_H3[(size_t)(c * NNB + s) * 256 + j];
        if (v) { any = true; acc = fmaxf(acc, h); }
    }
    out[(size_t)c * 256 + j] = any ? acc : 0.0f;
}

// ---------------- launcher ----------------------------------------------
extern "C" void kernel_launch(void* const* d_in, const int* in_sizes, int n_in,
                              void* d_out, int out_size) {
    const float* x  = (const float*)d_in[0];
    const float* W1 = (const float*)d_in[1];
    const float* b1 = (const float*)d_in[2];
    const float* W2 = (const float*)d_in[3];
    const float* b2 = (const float*)d_in[4];
    const float* W3 = (const float*)d_in[5];
    const float* b3 = (const float*)d_in[6];
    float* out = (float*)d_out;

    cudaFuncSetAttribute(knn_kernel, cudaFuncAttributeMaxDynamicSharedMemorySize, 65536);

    prep_kernel<<<144, 256>>>(x, W1, b1, W2, b2, W3, b3);
    pad_kernel<<<(NROWS + 255) / 256, 256>>>();
    fps_kernel<<<CLSZ, 256>>>();
    knn_kernel<<<M_CTR / 4, 128, 65536>>>();
    gather_kernel<<<NROWS / 4, 128>>>(x);
    sgemm_kernel<0><<<dim3(NROWS / 128, 1), 256>>>();
    sgemm_kernel<1><<<dim3(NROWS / 128, 1), 256>>>();
    sgemm_kernel<2><<<dim3(NROWS / 128, 2), 256>>>();
    pool_kernel<<<M_CTR, 256>>>(out);
}

// round 5
// speedup vs baseline: 5.4214x; 1.6729x over previous
#include <cuda_runtime.h>
#include <cuda_bf16.h>
#include <cstdint>

typedef unsigned long long u64;

#define N_PTS 16384
#define M_CTR 4096
#define NNB   32
#define R2F   0.04f
#define NROWS (M_CTR*NNB)
#define KP    144
#define CAP   256
#define CLSZ  8               // FPS cluster size
#define PPC   (N_PTS/CLSZ)    // 2048 points per CTA
#define FPT   8               // points per thread (256 thr/CTA)

// ---------------- device scratch ----------------------------------------
__device__ __align__(16) float4 g_pos4[N_PTS];
__device__ __align__(16) float4 g_center[M_CTR];
__device__ int   g_cols[NROWS];
__device__ int   g_cnt[M_CTR];
__device__ int   g_off[M_CTR];
__device__ int   g_nv;
__device__ int   g_rows[NROWS];
__device__ __align__(16) float g_W1p[KP*128];
__device__ __align__(16) float g_W2p[KP*128];
__device__ __align__(16) float g_W3p[KP*256];
__device__ __align__(16) float g_A [(size_t)NROWS*KP];
__device__ __align__(16) float g_H1[(size_t)NROWS*KP];
__device__ __align__(16) float g_H2[(size_t)NROWS*KP];
__device__ __align__(16) float g_H3[(size_t)NROWS*256];

// ---------------- f32x2 helpers -----------------------------------------
__device__ __forceinline__ u64 pk(float lo, float hi) {
    u64 r; asm("mov.b64 %0,{%1,%2};" : "=l"(r) : "f"(lo), "f"(hi)); return r;
}
__device__ __forceinline__ void upk(float& lo, float& hi, u64 v) {
    asm("mov.b64 {%0,%1},%2;" : "=f"(lo), "=f"(hi) : "l"(v));
}
__device__ __forceinline__ u64 add2(u64 a, u64 b) {
    u64 r; asm("add.rn.f32x2 %0,%1,%2;" : "=l"(r) : "l"(a), "l"(b)); return r;
}
__device__ __forceinline__ u64 mul2(u64 a, u64 b) {
    u64 r; asm("mul.rn.f32x2 %0,%1,%2;" : "=l"(r) : "l"(a), "l"(b)); return r;
}
__device__ __forceinline__ u64 fma2(u64 a, u64 b, u64 c) {
    u64 r; asm("fma.rn.f32x2 %0,%1,%2,%3;" : "=l"(r) : "l"(a), "l"(b), "l"(c)); return r;
}
// key = (positive f32 bits << 32) | ~oidx : u64 max == (max val, tie -> min idx)
__device__ __forceinline__ u64 mkkey(float v, int oidx) {
    return ((u64)__float_as_uint(v) << 32) | (u64)(unsigned)(~oidx);
}

// ---------------- cluster / mbarrier PTX helpers -------------------------
__device__ __forceinline__ unsigned sh_u32(const void* p) {
    return (unsigned)__cvta_generic_to_shared(p);
}
__device__ __forceinline__ unsigned mapa_sh(unsigned addr, unsigned rank) {
    unsigned r;
    asm("mapa.shared::cluster.u32 %0, %1, %2;" : "=r"(r) : "r"(addr), "r"(rank));
    return r;
}
__device__ __forceinline__ void mbar_init(unsigned a, unsigned cnt) {
    asm volatile("mbarrier.init.shared.b64 [%0], %1;" :: "r"(a), "r"(cnt) : "memory");
}
__device__ __forceinline__ void mbar_expect_tx(unsigned a, unsigned bytes) {
    asm volatile("mbarrier.arrive.expect_tx.shared::cta.b64 _, [%0], %1;"
                 :: "r"(a), "r"(bytes) : "memory");
}
__device__ __forceinline__ void st_async_u64(unsigned a, u64 v, unsigned mbar) {
    asm volatile("st.async.shared::cluster.mbarrier::complete_tx::bytes.b64 [%0], %1, [%2];"
                 :: "r"(a), "l"(v), "r"(mbar) : "memory");
}
__device__ __forceinline__ void st_async_u32(unsigned a, unsigned v, unsigned mbar) {
    asm volatile("st.async.shared::cluster.mbarrier::complete_tx::bytes.b32 [%0], %1, [%2];"
                 :: "r"(a), "r"(v), "r"(mbar) : "memory");
}
__device__ __forceinline__ void mbar_wait_cluster(unsigned a, int phase) {
    asm volatile(
        "{\n\t"
        ".reg .pred P;\n\t"
        "W_%=:\n\t"
        "mbarrier.try_wait.parity.acquire.cluster.shared::cta.b64 P, [%0], %1, 0x989680;\n\t"
        "@P bra.uni D_%=;\n\t"
        "bra.uni W_%=;\n\t"
        "D_%=:\n\t"
        "}" :: "r"(a), "r"(phase) : "memory");
}
__device__ __forceinline__ void cluster_sync_all() {
    asm volatile("barrier.cluster.arrive.aligned;" ::: "memory");
    asm volatile("barrier.cluster.wait.aligned;" ::: "memory");
}
__device__ __forceinline__ unsigned redux_max_u32(unsigned v) {
    unsigned r;
    asm("redux.sync.max.u32 %0, %1, 0xffffffff;" : "=r"(r) : "r"(v));
    return r;
}

// ---------------- prep ----------------------------------------------------
__global__ void __launch_bounds__(256) prep_kernel(
    const float* __restrict__ x,
    const float* __restrict__ W1, const float* __restrict__ b1,
    const float* __restrict__ W2, const float* __restrict__ b2,
    const float* __restrict__ W3, const float* __restrict__ b3)
{
    int i = blockIdx.x * 256 + threadIdx.x;
    if (i < N_PTS) {
        const float* row = x + (size_t)i * 131;
        g_pos4[i] = make_float4(row[0], row[1], row[2], 0.f);
    }
    if (i < KP * 128) {
        int k = i >> 7, j = i & 127;
        g_W1p[i] = (k < 131) ? W1[k * 128 + j] : (k == 131 ? b1[j] : 0.f);
        g_W2p[i] = (k < 128) ? W2[k * 128 + j] : (k == 128 ? b2[j] : 0.f);
    }
    if (i < KP * 256) {
        int k = i >> 8, j = i & 255;
        g_W3p[i] = (k < 128) ? W3[k * 256 + j] : (k == 128 ? b3[j] : 0.f);
    }
}

// bias column for next GEMM: cols 128..143 of H1/H2 = (1,0,...,0)
__global__ void __launch_bounds__(256) pad_kernel() {
    int row = blockIdx.x * 256 + threadIdx.x;
    if (row >= NROWS) return;
    float4* p1 = (float4*)(g_H1 + (size_t)row * KP + 128);
    float4* p2 = (float4*)(g_H2 + (size_t)row * KP + 128);
    float4 one0 = make_float4(1.f, 0.f, 0.f, 0.f);
    float4 z    = make_float4(0.f, 0.f, 0.f, 0.f);
    p1[0] = one0; p1[1] = z; p1[2] = z; p1[3] = z;
    p2[0] = one0; p2[1] = z; p2[2] = z; p2[3] = z;
}

// ---------------- FPS: 8-CTA cluster, st.async exchange -------------------
__global__ void __launch_bounds__(256, 1) __cluster_dims__(CLSZ, 1, 1)
fps_kernel() {
    __shared__ __align__(16) u64    s_wkey[8];       // per-warp bests
    __shared__ __align__(16) float4 s_wxyz[8];
    __shared__ __align__(16) u64    s_mbk [2][CLSZ]; // mailbox keys (dbl buf)
    __shared__ __align__(16) u64    s_mbxy[2][CLSZ];
    __shared__ unsigned             s_mbz [2][CLSZ];
    __shared__ __align__(8)  u64    s_bar [2];

    int tid = threadIdx.x, lane = tid & 31, warp = tid >> 5;
    unsigned rank;
    asm("mov.u32 %0, %%cluster_ctarank;" : "=r"(rank));
    int pbase = (int)rank * PPC + tid;

    // coords + min_d fully register-resident
    u64 PX[4], PY[4], PZ[4];
    float m[FPT];
#pragma unroll
    for (int q = 0; q < 4; q++) {
        float4 a = g_pos4[pbase + (2 * q) * 256];
        float4 b = g_pos4[pbase + (2 * q + 1) * 256];
        PX[q] = pk(a.x, b.x); PY[q] = pk(a.y, b.y); PZ[q] = pk(a.z, b.z);
        m[2 * q] = __int_as_float(0x7f800000);
        m[2 * q + 1] = __int_as_float(0x7f800000);
    }

    if (tid == 0) {
        mbar_init(sh_u32(&s_bar[0]), 1);   // 1 local arrive (expect_tx) + 160 tx bytes
        mbar_init(sh_u32(&s_bar[1]), 1);
    }
    cluster_sync_all();     // barriers visible before any remote st.async

    float4 c0 = g_pos4[0];
    float cx = c0.x, cy = c0.y, cz = c0.z;
    if (rank == 0 && tid == 0) g_center[0] = make_float4(cx, cy, cz, 0.f);

    int par0 = 0, par1 = 0;

    for (int k = 1; k < M_CTR; k++) {
        int buf = k & 1;
        // post this phase's expected bytes early (8 senders x 20B)
        if (tid == 0) mbar_expect_tx(sh_u32(&s_bar[buf]), CLSZ * 20);

        // --- packed exact distance update (rn ops, (x2+y2)+z2, p+(-c)) ---
        u64 ncx = pk(-cx, -cx), ncy = pk(-cy, -cy), ncz = pk(-cz, -cz);
#pragma unroll
        for (int q = 0; q < 4; q++) {
            u64 dx = add2(PX[q], ncx);
            u64 dy = add2(PY[q], ncy);
            u64 dz = add2(PZ[q], ncz);
            u64 s  = add2(add2(mul2(dx, dx), mul2(dy, dy)), mul2(dz, dz));
            float d0, d1; upk(d0, d1, s);
            m[2 * q]     = fminf(m[2 * q], d0);
            m[2 * q + 1] = fminf(m[2 * q + 1], d1);
        }
        // --- per-thread argmax (first index on tie) ---
        float vmax = m[0];
#pragma unroll
        for (int i = 1; i < FPT; i++) vmax = fmaxf(vmax, m[i]);
        int idx = 0;
#pragma unroll
        for (int i = FPT - 1; i >= 0; i--) if (m[i] == vmax) idx = i;
        u64 key = mkkey(vmax, pbase + idx * 256);
        float bx = 0.f, by = 0.f, bz = 0.f;
#pragma unroll
        for (int q = 0; q < 4; q++) {
            if ((idx >> 1) == q) {
                float lo, hi;
                upk(lo, hi, PX[q]); bx = (idx & 1) ? hi : lo;
                upk(lo, hi, PY[q]); by = (idx & 1) ? hi : lo;
                upk(lo, hi, PZ[q]); bz = (idx & 1) ? hi : lo;
            }
        }
        // --- warp argmax via redux (max vbits, tie -> max ~oidx = min oidx) ---
        {
            unsigned vb = (unsigned)(key >> 32);
            unsigned mx = redux_max_u32(vb);
            unsigned cand = (vb == mx) ? (unsigned)key : 0u;
            unsigned lw = redux_max_u32(cand);
            unsigned ball = __ballot_sync(0xffffffffu, cand == lw && vb == mx);
            int src = __ffs(ball) - 1;
            bx = __shfl_sync(0xffffffffu, bx, src);
            by = __shfl_sync(0xffffffffu, by, src);
            bz = __shfl_sync(0xffffffffu, bz, src);
            key = ((u64)mx << 32) | lw;
        }
        if (lane == 0) { s_wkey[warp] = key; s_wxyz[warp] = make_float4(bx, by, bz, 0.f); }
        __syncthreads();
        // --- CTA reduce in warp0, then st.async CTA-best to all ranks ------
        if (warp == 0) {
            u64 kk = s_wkey[lane & 7];
            float4 w = s_wxyz[lane & 7];
#pragma unroll
            for (int o = 4; o; o >>= 1) {
                u64  ok = __shfl_xor_sync(0xffffffffu, kk, o);
                float ox = __shfl_xor_sync(0xffffffffu, w.x, o);
                float oy = __shfl_xor_sync(0xffffffffu, w.y, o);
                float oz = __shfl_xor_sync(0xffffffffu, w.z, o);
                if (ok > kk) { kk = ok; w.x = ox; w.y = oy; w.z = oz; }
            }
            if (lane < CLSZ) {
                unsigned dst = (unsigned)lane;
                unsigned ab = mapa_sh(sh_u32(&s_bar [buf]),       dst);
                unsigned ak = mapa_sh(sh_u32(&s_mbk [buf][rank]), dst);
                unsigned ax = mapa_sh(sh_u32(&s_mbxy[buf][rank]), dst);
                unsigned az = mapa_sh(sh_u32(&s_mbz [buf][rank]), dst);
                st_async_u64(ak, kk, ab);
                st_async_u64(ax, pk(w.x, w.y), ab);
                st_async_u32(az, __float_as_uint(w.z), ab);
            }
        }
        // --- wait for all 160 bytes, pick global winner locally -----------
        mbar_wait_cluster(sh_u32(&s_bar[buf]), buf ? par1 : par0);
        if (buf) par1 ^= 1; else par0 ^= 1;

        u64 best = s_mbk[buf][0];
        int br = 0;
#pragma unroll
        for (int r = 1; r < CLSZ; r++) {
            u64 kr = s_mbk[buf][r];
            if (kr > best) { best = kr; br = r; }
        }
        float lo, hi; upk(lo, hi, s_mbxy[buf][br]);
        cx = lo; cy = hi; cz = __uint_as_float(s_mbz[buf][br]);
        if (rank == 0 && tid == 0) g_center[k] = make_float4(cx, cy, cz, 0.f);
    }
    cluster_sync_all();
}

// ---------------- radius-KNN ----------------------------------------------
__global__ void __launch_bounds__(128) knn_kernel() {
    extern __shared__ float4 s_t[];                  // 4096 float4 = 64KB
    __shared__ u64 s_list[4][CAP];
    int tid = threadIdx.x, lane = tid & 31, warp = tid >> 5;
    int c = blockIdx.x * 4 + warp;
    float4 ct = g_center[c];

    int cnt = 0;
    for (int tile = 0; tile < 4; tile++) {
        __syncthreads();
        for (int i = tid; i < 4096; i += 128) s_t[i] = g_pos4[tile * 4096 + i];
        __syncthreads();
        for (int i = lane; i < 4096; i += 32) {
            float4 p = s_t[i];
            float dx = __fsub_rn(ct.x, p.x);
            float dy = __fsub_rn(ct.y, p.y);
            float dz = __fsub_rn(ct.z, p.z);
            float d2 = __fadd_rn(__fadd_rn(__fmul_rn(dx, dx), __fmul_rn(dy, dy)),
                                 __fmul_rn(dz, dz));
            bool ok = d2 <= R2F;
            unsigned mk = __ballot_sync(0xffffffffu, ok);
            if (ok) {
                int pos = cnt + __popc(mk & ((1u << lane) - 1u));
                if (pos < CAP)
                    s_list[warp][pos] =
                        ((u64)__float_as_uint(d2) << 32) | (unsigned)(tile * 4096 + i);
            }
            cnt += __popc(mk);
        }
    }
    if (cnt > CAP) cnt = CAP;
    __syncwarp();

    if (cnt <= NNB) {
        int v = (lane < cnt) ? (int)(unsigned)(s_list[warp][lane] & 0xffffffffu) : -1;
        g_cols[c * NNB + lane] = v;
        if (lane == 0) g_cnt[c] = cnt;
    } else {
        for (int i = lane; i < cnt; i += 32) {
            u64 ki = s_list[warp][i];
            int rank = 0;
            for (int j = 0; j < cnt; j++) rank += (s_list[warp][j] < ki);
            if (rank < NNB)
                g_cols[c * NNB + rank] = (int)(unsigned)(ki & 0xffffffffu);
        }
        if (lane == 0) g_cnt[c] = NNB;
    }
}

// ---------------- exclusive scan of g_cnt (single CTA) ---------------------
__global__ void __launch_bounds__(512, 1) scan_kernel() {
    __shared__ int s_ws[16];
    int tid = threadIdx.x, lane = tid & 31, warp = tid >> 5;
    int v[8], run = 0;
#pragma unroll
    for (int i = 0; i < 8; i++) { v[i] = g_cnt[tid * 8 + i]; run += v[i]; }
    int tot = run;
    int pre = tot;
#pragma unroll
    for (int o = 1; o < 32; o <<= 1) {
        int t = __shfl_up_sync(0xffffffffu, pre, o);
        if (lane >= o) pre += t;
    }
    if (lane == 31) s_ws[warp] = pre;
    int excl = pre - tot;                       // exclusive within warp
    __syncthreads();
    if (warp == 0) {
        int w = (lane < 16) ? s_ws[lane] : 0;
#pragma unroll
        for (int o = 1; o < 16; o <<= 1) {
            int t = __shfl_up_sync(0xffffffffu, w, o);
            if (lane >= o) w += t;
        }
        if (lane < 16) s_ws[lane] = w;
    }
    __syncthreads();
    int base = (warp > 0) ? s_ws[warp - 1] : 0;
    int off = base + excl;
#pragma unroll
    for (int i = 0; i < 8; i++) { g_off[tid * 8 + i] = off; off += v[i]; }
    if (tid == 511) g_nv = off;
}

// ---------------- row map: compacted row -> (center,slot) ------------------
__global__ void __launch_bounds__(256) rowmap_kernel() {
    int idx = blockIdx.x * 256 + threadIdx.x;   // 131072 threads
    int c = idx >> 5, s = idx & 31;
    if (s < g_cnt[c]) g_rows[g_off[c] + s] = idx;
}

// ---------------- gather (compacted rows only, grid-stride) ----------------
__global__ void __launch_bounds__(256) gather_kernel(const float* __restrict__ x) {
    int lane = threadIdx.x & 31;
    int warp = threadIdx.x >> 5;
    int nv = g_nv;
    for (int r = blockIdx.x * 8 + warp; r < nv; r += 512 * 8) {
        int rid = g_rows[r];
        int c   = rid >> 5;
        int col = g_cols[rid];
        float* a = g_A + (size_t)r * KP;
        const float* xr = x + (size_t)col * 131 + 3 + 4 * lane;
        ((float4*)a)[lane] = make_float4(xr[0], xr[1], xr[2], xr[3]);
        if (lane < 4) {
            float4 e = make_float4(0.f, 0.f, 0.f, 0.f);
            if (lane == 0) {
                float4 p = g_pos4[col]; float4 ct = g_center[c];
                e = make_float4(p.x - ct.x, p.y - ct.y, p.z - ct.z, 1.0f);
            }
            ((float4*)a)[32 + lane] = e;
        }
    }
}

// ---------------- tiled fp32 GEMM + relu (early-exit past NV) --------------
template<int L>
__global__ void __launch_bounds__(256) sgemm_kernel() {
    size_t bRow = (size_t)blockIdx.x * 128;
    if ((int)bRow >= g_nv) return;
    const float* A = (L == 0) ? g_A  : (L == 1) ? g_H1 : g_H2;
    const float* B = (L == 0) ? g_W1p : (L == 1) ? g_W2p : g_W3p;
    float*       C = (L == 0) ? g_H1 : (L == 1) ? g_H2 : g_H3;
    const int ldb = (L == 2) ? 256 : 128;
    const int ldc = (L == 2) ? 256 : KP;

    __shared__ __align__(16) float As[16][132];
    __shared__ __align__(16) float Bs[16][132];
    int t  = threadIdx.x;
    int tx = t & 15, ty = t >> 4;
    int    bCol = blockIdx.y * 128;

    u64 acc[8][4];
#pragma unroll
    for (int i = 0; i < 8; i++)
#pragma unroll
        for (int p = 0; p < 4; p++) acc[i][p] = 0ull;

    for (int k0 = 0; k0 < KP; k0 += 16) {
#pragma unroll
        for (int e2 = 0; e2 < 2; e2++) {
            int e = t * 2 + e2;
            int r = e >> 2, c4 = e & 3;
            float4 f = *(const float4*)(A + (bRow + r) * KP + k0 + c4 * 4);
            As[c4 * 4 + 0][r] = f.x; As[c4 * 4 + 1][r] = f.y;
            As[c4 * 4 + 2][r] = f.z; As[c4 * 4 + 3][r] = f.w;
        }
#pragma unroll
        for (int e2 = 0; e2 < 2; e2++) {
            int e = t * 2 + e2;
            int r = e >> 5, c4 = e & 31;
            *(float4*)&Bs[r][c4 * 4] =
                *(const float4*)(B + (size_t)(k0 + r) * ldb + bCol + c4 * 4);
        }
        __syncthreads();
#pragma unroll
        for (int kk = 0; kk < 16; kk++) {
            float a[8]; u64 b[4];
            const u64* bp = (const u64*)&Bs[kk][tx * 8];
#pragma unroll
            for (int p = 0; p < 4; p++) b[p] = bp[p];
#pragma unroll
            for (int i = 0; i < 8; i++) a[i] = As[kk][ty * 8 + i];
#pragma unroll
            for (int i = 0; i < 8; i++) {
                u64 aa = pk(a[i], a[i]);
#pragma unroll
                for (int p = 0; p < 4; p++) acc[i][p] = fma2(aa, b[p], acc[i][p]);
            }
        }
        __syncthreads();
    }
#pragma unroll
    for (int i = 0; i < 8; i++) {
        float* cr = C + (bRow + ty * 8 + i) * (size_t)ldc + bCol + tx * 8;
#pragma unroll
        for (int p = 0; p < 4; p++) {
            float lo, hi; upk(lo, hi, acc[i][p]);
            ((float2*)cr)[p] = make_float2(fmaxf(lo, 0.f), fmaxf(hi, 0.f));
        }
    }
}

// ---------------- masked max-pool over compacted rows ----------------------
__global__ void __launch_bounds__(256) pool_kernel(float* __restrict__ out) {
    int c = blockIdx.x, j = threadIdx.x;
    int off = g_off[c], cnt = g_cnt[c];
    float acc = 0.0f;
    if (cnt > 0) {
        acc = g_H3[(size_t)off * 256 + j];
        for (int s = 1; s < cnt; s++)
            acc = fmaxf(acc, g_H3[(size_t)(off + s) * 256 + j]);
    }
    out[(size_t)c * 256 + j] = acc;
}

// ---------------- launcher ----------------------------------------------
extern "C" void kernel_launch(void* const* d_in, const int* in_sizes, int n_in,
                              void* d_out, int out_size) {
    const float* x  = (const float*)d_in[0];
    const float* W1 = (const float*)d_in[1];
    const float* b1 = (const float*)d_in[2];
    const float* W2 = (const float*)d_in[3];
    const float* b2 = (const float*)d_in[4];
    const float* W3 = (const float*)d_in[5];
    const float* b3 = (const float*)d_in[6];
    float* out = (float*)d_out;

    cudaFuncSetAttribute(knn_kernel, cudaFuncAttributeMaxDynamicSharedMemorySize, 65536);

    prep_kernel<<<144, 256>>>(x, W1, b1, W2, b2, W3, b3);
    pad_kernel<<<(NROWS + 255) / 256, 256>>>();
    fps_kernel<<<CLSZ, 256>>>();
    knn_kernel<<<M_CTR / 4, 128, 65536>>>();
    scan_kernel<<<1, 512>>>();
    rowmap_kernel<<<NROWS / 256, 256>>>();
    gather_kernel<<<512, 256>>>(x);
    sgemm_kernel<0><<<dim3(NROWS / 128, 1), 256>>>();
    sgemm_kernel<1><<<dim3(NROWS / 128, 1), 256>>>();
    sgemm_kernel<2><<<dim3(NROWS / 128, 2), 256>>>();
    pool_kernel<<<M_CTR, 256>>>(out);
}